// round 15
// baseline (speedup 1.0000x reference)
#include <cuda_runtime.h>
#include <cstdint>
#include <cstddef>

// ---------------- problem constants ----------------
#define S_TOK   8192
#define MDIM    1024
#define NEXP    8
#define FFN     4096
#define CAP     1024

// ---------------- device scratch ----------------
__device__ int   g_expert_of_token[S_TOK];
__device__ float g_gate_of_token[S_TOK];
__device__ int   g_expert_tokens[NEXP * CAP];
__device__ float g_gate_slot[NEXP * CAP];
__device__ float g_zero[MDIM] = {};                    // zero row for dropped slots
__device__ float g_xr [(size_t)S_TOK * MDIM];          // tf32-rounded x
__device__ float g_H  [(size_t)NEXP * CAP * FFN];      // hidden (tf32-rounded at write)

// ---------------- helpers ----------------
__device__ __forceinline__ uint32_t smem_u32(const void* p) {
    uint32_t a;
    asm("{ .reg .u64 t; cvta.to.shared.u64 t, %1; cvt.u32.u64 %0, t; }" : "=r"(a) : "l"(p));
    return a;
}
__device__ __forceinline__ float rna_tf32(float x) {
    uint32_t u;
    asm("cvt.rna.tf32.f32 %0, %1;" : "=r"(u) : "f"(x));
    return __uint_as_float(u);
}
__device__ __forceinline__ uint32_t rna_tf32_u(float x) {
    uint32_t u;
    asm("cvt.rna.tf32.f32 %0, %1;" : "=r"(u) : "f"(x));
    return u;
}
__device__ __forceinline__ void mma_tf32(float* c, const uint32_t* a, const uint32_t* b) {
    asm volatile(
        "mma.sync.aligned.m16n8k8.row.col.f32.tf32.tf32.f32 "
        "{%0,%1,%2,%3}, {%4,%5,%6,%7}, {%8,%9}, {%0,%1,%2,%3};"
        : "+f"(c[0]), "+f"(c[1]), "+f"(c[2]), "+f"(c[3])
        : "r"(a[0]), "r"(a[1]), "r"(a[2]), "r"(a[3]), "r"(b[0]), "r"(b[1]));
}
__device__ __forceinline__ void ldsm4(uint32_t* r, uint32_t addr) {
    asm volatile("ldmatrix.sync.aligned.m8n8.x4.shared.b16 {%0,%1,%2,%3}, [%4];"
        : "=r"(r[0]), "=r"(r[1]), "=r"(r[2]), "=r"(r[3]) : "r"(addr));
}
__device__ __forceinline__ void cp16(uint32_t dst, const float* src) {
    asm volatile("cp.async.cg.shared.global [%0], [%1], 16;" :: "r"(dst), "l"(src));
}

// ---------------- K1: gating (+ fused x rounding), 32 tokens/block ----------------
__global__ void __launch_bounds__(1024) gate_kernel(const float* __restrict__ x,
                                                    const float* __restrict__ wg) {
    __shared__ float shw[NEXP][MDIM];   // 32 KB
    int tid = threadIdx.x;
    for (int idx = tid; idx < MDIM * NEXP; idx += 1024) {
        int k = idx >> 3, e = idx & 7;
        shw[e][k] = wg[idx];
    }
    __syncthreads();

    int warp = tid >> 5, lane = tid & 31;
    int s = blockIdx.x * 32 + warp;
    const float* xr = x + (size_t)s * MDIM;
    float* xo = g_xr + (size_t)s * MDIM;

    float acc[NEXP];
#pragma unroll
    for (int e = 0; e < NEXP; e++) acc[e] = 0.f;
#pragma unroll
    for (int i = 0; i < 8; i++) {
        float4 xv = *(const float4*)(xr + i * 128 + lane * 4);
#pragma unroll
        for (int e = 0; e < NEXP; e++) {
            float4 wv = *(const float4*)&shw[e][i * 128 + lane * 4];
            acc[e] += xv.x * wv.x + xv.y * wv.y + xv.z * wv.z + xv.w * wv.w;
        }
        float4 rv;
        rv.x = rna_tf32(xv.x); rv.y = rna_tf32(xv.y);
        rv.z = rna_tf32(xv.z); rv.w = rna_tf32(xv.w);
        *(float4*)(xo + i * 128 + lane * 4) = rv;
    }
#pragma unroll
    for (int e = 0; e < NEXP; e++) {
#pragma unroll
        for (int off = 16; off; off >>= 1)
            acc[e] += __shfl_xor_sync(0xffffffffu, acc[e], off);
    }
    if (lane == 0) {
        float best = acc[0]; int bi = 0;
#pragma unroll
        for (int e = 1; e < NEXP; e++)
            if (acc[e] > best) { best = acc[e]; bi = e; }
        float sum = 0.f;
#pragma unroll
        for (int e = 0; e < NEXP; e++) sum += __expf(acc[e] - best);
        g_expert_of_token[s] = bi;
        g_gate_of_token[s]   = 1.0f / sum;
    }
}

// ---------------- K2: per-expert rank scan + dropped-row zeroing ----------------
__global__ void scan_kernel(float* __restrict__ out) {
    int e = blockIdx.x;
    int t = threadIdx.x;             // 1024 threads
    int lane = t & 31, w = t >> 5;

    g_expert_tokens[e * CAP + t] = -1;
    g_gate_slot[e * CAP + t] = 0.f;

    int base = t * 8;
    int cnt = 0;
    int loc[8];
#pragma unroll
    for (int j = 0; j < 8; j++) {
        loc[j] = cnt;
        if (g_expert_of_token[base + j] == e) cnt++;
    }

    int incl = cnt;
#pragma unroll
    for (int off = 1; off < 32; off <<= 1) {
        int v = __shfl_up_sync(0xffffffffu, incl, off);
        if (lane >= off) incl += v;
    }
    __shared__ int wsum[32];
    __shared__ int ndrop;
    __shared__ int drop_list[S_TOK - CAP];
    if (t == 0) ndrop = 0;
    if (lane == 31) wsum[w] = incl;
    __syncthreads();
    if (w == 0) {
        int v2 = wsum[lane];
#pragma unroll
        for (int off = 1; off < 32; off <<= 1) {
            int u = __shfl_up_sync(0xffffffffu, v2, off);
            if (lane >= off) v2 += u;
        }
        wsum[lane] = v2;
    }
    __syncthreads();
    int excl = (w > 0 ? wsum[w - 1] : 0) + incl - cnt;

#pragma unroll
    for (int j = 0; j < 8; j++) {
        int s = base + j;
        if (g_expert_of_token[s] == e) {
            int c = excl + loc[j];
            if (c < CAP) {
                g_expert_tokens[e * CAP + c] = s;
                g_gate_slot[e * CAP + c]     = g_gate_of_token[s];
            } else {
                int d = atomicAdd(&ndrop, 1);
                drop_list[d] = s;
            }
        }
    }
    __syncthreads();

    int nd = ndrop;
    for (int d = 0; d < nd; d++) {
        int s = drop_list[d];
        out[(size_t)s * MDIM + t] = 0.f;
    }
}

// ---------------- K3: tf32 mma.sync GEMM — warp tile 128x32, bf double-buffered ----------------
// C tile 256x128, BK=64, 8 warps (2M x 4N), warp tile 128x32.
// A k-major in SMEM [256][68] (ldmatrix.x4, 8 frags/kk).
// B native row-major [64][136] (scalar LDS + cvt, 4 n-frags/kk, double-buffered across kk).
#define BM 256
#define BN 128
#define BK 64
#define APAD 68
#define BPAD 136
#define A_FLOATS (BM * APAD)                          // 17408
#define B_FLOATS (BK * BPAD)                          // 8704
#define STAGE_B  ((A_FLOATS + B_FLOATS) * 4)          // 104448 bytes
#define TAB_OFF  (2 * STAGE_B)
#define GEMM_SMEM (2 * STAGE_B + BM * 8)              // +2KB ptr table

template<int K_TOTAL, int NDIM, bool IS_G2>
__global__ void __launch_bounds__(256, 1) mma_gemm(const float* __restrict__ W,
                                                   float* __restrict__ OUT) {
    constexpr int CITER = K_TOTAL / BK;
    extern __shared__ char smraw[];
    uint32_t sbase = smem_u32(smraw);
    const float** tab = (const float**)(smraw + TAB_OFF);

    int tid = threadIdx.x;
    int wid = tid >> 5, lane = tid & 31;
    int wm = wid & 1, wn = wid >> 1;     // 2 M-groups x 4 N-groups
    int g = lane >> 2, tg = lane & 3;

    int m0 = blockIdx.y * BM;
    int n0 = blockIdx.x * BN;
    int e  = m0 >> 10;

    const float* Wexp = W + (size_t)e * ((size_t)MDIM * FFN);

    // ---- G1: gathered row-pointer table in SMEM ----
    if (!IS_G2) {
        int tok = g_expert_tokens[m0 + tid];
        tab[tid] = (tok >= 0) ? (g_xr + (size_t)tok * MDIM) : g_zero;
        __syncthreads();
    }

    // ---- affine cp.async addressing ----
    int arow = tid >> 4, ach = tid & 15;               // A: 16 rows/thread-group
    uint32_t daA = ((uint32_t)(arow * APAD + ach * 4)) * 4u;
    const float* Abase = IS_G2 ? (g_H + (size_t)(m0 + arow) * FFN + ach * 4) : nullptr;

    int brow = tid >> 5, bch = tid & 31;               // B: [64][128], 8 rows/thread-group
    uint32_t daB = ((uint32_t)(A_FLOATS + brow * BPAD + bch * 4)) * 4u;
    const float* Bbase = Wexp + (size_t)brow * NDIM + n0 + bch * 4;

    auto load_stage = [&](int s, int k0) {
        uint32_t sb = sbase + (uint32_t)s * STAGE_B;
#pragma unroll
        for (int i = 0; i < 16; i++) {
            uint32_t d = sb + daA + (uint32_t)i * (16 * APAD * 4);
            if (IS_G2) cp16(d, Abase + (size_t)i * (16 * FFN) + k0);
            else       cp16(d, tab[arow + 16 * i] + k0 + ach * 4);
        }
#pragma unroll
        for (int i = 0; i < 8; i++)
            cp16(sb + daB + (uint32_t)i * (8 * BPAD * 4),
                 Bbase + ((size_t)k0 + 8 * i) * NDIM);
        asm volatile("cp.async.commit_group;" ::: "memory");
    };

    load_stage(0, 0);

    // ---- ldmatrix per-lane A fragment addresses (8 M-tiles of 16 rows) ----
    uint32_t aoff[8];
    {
        uint32_t ar = (uint32_t)((lane & 7) + 8 * ((lane >> 3) & 1));
        uint32_t ac = (uint32_t)(((lane >> 4) & 1) * 4);
#pragma unroll
        for (int mi = 0; mi < 8; mi++)
            aoff[mi] = ((wm * 128 + mi * 16 + ar) * APAD + ac) * 4u;
    }

    float acc[8][4][4];
#pragma unroll
    for (int mi = 0; mi < 8; mi++)
#pragma unroll
        for (int ni = 0; ni < 4; ni++)
#pragma unroll
            for (int q = 0; q < 4; q++) acc[mi][ni][q] = 0.f;

    uint32_t bfb[2][4][2];   // B fragments, double-buffered across kk

    for (int c = 0; c < CITER; c++) {
        int s = c & 1;
        asm volatile("cp.async.wait_group 0;" ::: "memory");
        __syncthreads();
        if (c + 1 < CITER) load_stage(s ^ 1, (c + 1) * BK);

        uint32_t ab = sbase + (uint32_t)s * STAGE_B;
        const float* Bs = (const float*)(smraw + (size_t)s * STAGE_B) + A_FLOATS;

        // prime B fragments for kk=0
#pragma unroll
        for (int ni = 0; ni < 4; ni++) {
            int cc = wn * 32 + ni * 8 + g;
            bfb[0][ni][0] = rna_tf32_u(Bs[tg * BPAD + cc]);
            bfb[0][ni][1] = rna_tf32_u(Bs[(tg + 4) * BPAD + cc]);
        }

#pragma unroll
        for (int kk = 0; kk < 8; kk++) {
            int cur = kk & 1;
            // A fragments for this kk
            uint32_t af[8][4];
#pragma unroll
            for (int mi = 0; mi < 8; mi++)
                ldsm4(af[mi], ab + aoff[mi] + (uint32_t)kk * 32);
            // B fragments for kk+1 (latency hidden behind this kk's 32 MMAs)
            if (kk + 1 < 8) {
                int kb2 = (kk + 1) * 8;
#pragma unroll
                for (int ni = 0; ni < 4; ni++) {
                    int cc = wn * 32 + ni * 8 + g;
                    bfb[cur ^ 1][ni][0] = rna_tf32_u(Bs[(kb2 + tg) * BPAD + cc]);
                    bfb[cur ^ 1][ni][1] = rna_tf32_u(Bs[(kb2 + tg + 4) * BPAD + cc]);
                }
            }
#pragma unroll
            for (int mi = 0; mi < 8; mi++)
#pragma unroll
                for (int ni = 0; ni < 4; ni++)
                    mma_tf32(acc[mi][ni], af[mi], bfb[cur][ni]);
        }
    }

    // ---------------- epilogue ----------------
    if (!IS_G2) {
#pragma unroll
        for (int mi = 0; mi < 8; mi++) {
            int r0 = m0 + wm * 128 + mi * 16 + g;
#pragma unroll
            for (int ni = 0; ni < 4; ni++) {
                int cc = n0 + wn * 32 + ni * 8 + 2 * tg;
                float2 v0, v1;
                v0.x = rna_tf32(fmaxf(acc[mi][ni][0], 0.f));
                v0.y = rna_tf32(fmaxf(acc[mi][ni][1], 0.f));
                v1.x = rna_tf32(fmaxf(acc[mi][ni][2], 0.f));
                v1.y = rna_tf32(fmaxf(acc[mi][ni][3], 0.f));
                *(float2*)&g_H[(size_t)r0 * FFN + cc]       = v0;
                *(float2*)&g_H[(size_t)(r0 + 8) * FFN + cc] = v1;
            }
        }
    } else {
#pragma unroll
        for (int mi = 0; mi < 8; mi++) {
            int r0 = m0 + wm * 128 + mi * 16 + g;
            int tokA = g_expert_tokens[r0];
            int tokB = g_expert_tokens[r0 + 8];
            float gA = g_gate_slot[r0];
            float gB = g_gate_slot[r0 + 8];
#pragma unroll
            for (int ni = 0; ni < 4; ni++) {
                int cc = n0 + wn * 32 + ni * 8 + 2 * tg;
                if (tokA >= 0) {
                    float2 v; v.x = gA * acc[mi][ni][0]; v.y = gA * acc[mi][ni][1];
                    *(float2*)&OUT[(size_t)tokA * MDIM + cc] = v;
                }
                if (tokB >= 0) {
                    float2 v; v.x = gB * acc[mi][ni][2]; v.y = gB * acc[mi][ni][3];
                    *(float2*)&OUT[(size_t)tokB * MDIM + cc] = v;
                }
            }
        }
    }
}

// ---------------- launch ----------------
extern "C" void kernel_launch(void* const* d_in, const int* in_sizes, int n_in,
                              void* d_out, int out_size) {
    const float* x  = (const float*)d_in[0];
    const float* wg = (const float*)d_in[1];
    const float* w1 = (const float*)d_in[2];
    const float* w2 = (const float*)d_in[3];
    float* out = (float*)d_out;

    static bool attr_done = false;
    if (!attr_done) {
        cudaFuncSetAttribute(mma_gemm<MDIM, FFN,  false>,
                             cudaFuncAttributeMaxDynamicSharedMemorySize, GEMM_SMEM);
        cudaFuncSetAttribute(mma_gemm<FFN,  MDIM, true>,
                             cudaFuncAttributeMaxDynamicSharedMemorySize, GEMM_SMEM);
        attr_done = true;
    }

    gate_kernel<<<S_TOK / 32, 1024>>>(x, wg);
    scan_kernel<<<NEXP, 1024>>>(out);

    mma_gemm<MDIM, FFN,  false><<<dim3(FFN / BN,  (NEXP * CAP) / BM), 256, GEMM_SMEM>>>(w1, nullptr);
    mma_gemm<FFN,  MDIM, true ><<<dim3(MDIM / BN, (NEXP * CAP) / BM), 256, GEMM_SMEM>>>(w2, out);
}

// round 16
// speedup vs baseline: 1.0030x; 1.0030x over previous
#include <cuda_runtime.h>
#include <cstdint>
#include <cstddef>

// ---------------- problem constants ----------------
#define S_TOK   8192
#define MDIM    1024
#define NEXP    8
#define FFN     4096
#define CAP     1024

// ---------------- device scratch ----------------
__device__ int   g_expert_of_token[S_TOK];
__device__ float g_gate_of_token[S_TOK];
__device__ int   g_expert_tokens[NEXP * CAP];
__device__ float g_gate_slot[NEXP * CAP];
__device__ float g_zero[MDIM] = {};                    // zero row for dropped slots
__device__ float g_xr [(size_t)S_TOK * MDIM];          // tf32-rounded x
__device__ float g_H  [(size_t)NEXP * CAP * FFN];      // hidden (tf32-rounded at write)

// ---------------- helpers ----------------
__device__ __forceinline__ uint32_t smem_u32(const void* p) {
    uint32_t a;
    asm("{ .reg .u64 t; cvta.to.shared.u64 t, %1; cvt.u32.u64 %0, t; }" : "=r"(a) : "l"(p));
    return a;
}
__device__ __forceinline__ float rna_tf32(float x) {
    uint32_t u;
    asm("cvt.rna.tf32.f32 %0, %1;" : "=r"(u) : "f"(x));
    return __uint_as_float(u);
}
__device__ __forceinline__ uint32_t rna_tf32_u(float x) {
    uint32_t u;
    asm("cvt.rna.tf32.f32 %0, %1;" : "=r"(u) : "f"(x));
    return u;
}
__device__ __forceinline__ void mma_tf32(float* c, const uint32_t* a, const uint32_t* b) {
    asm volatile(
        "mma.sync.aligned.m16n8k8.row.col.f32.tf32.tf32.f32 "
        "{%0,%1,%2,%3}, {%4,%5,%6,%7}, {%8,%9}, {%0,%1,%2,%3};"
        : "+f"(c[0]), "+f"(c[1]), "+f"(c[2]), "+f"(c[3])
        : "r"(a[0]), "r"(a[1]), "r"(a[2]), "r"(a[3]), "r"(b[0]), "r"(b[1]));
}
__device__ __forceinline__ void ldsm4(uint32_t* r, uint32_t addr) {
    asm volatile("ldmatrix.sync.aligned.m8n8.x4.shared.b16 {%0,%1,%2,%3}, [%4];"
        : "=r"(r[0]), "=r"(r[1]), "=r"(r[2]), "=r"(r[3]) : "r"(addr));
}
__device__ __forceinline__ void cp16(uint32_t dst, const float* src) {
    asm volatile("cp.async.cg.shared.global [%0], [%1], 16;" :: "r"(dst), "l"(src));
}

// ---------------- K1: gating (+ fused x rounding), 32 tokens/block ----------------
__global__ void __launch_bounds__(1024) gate_kernel(const float* __restrict__ x,
                                                    const float* __restrict__ wg) {
    __shared__ float shw[NEXP][MDIM];   // 32 KB
    int tid = threadIdx.x;
    for (int idx = tid; idx < MDIM * NEXP; idx += 1024) {
        int k = idx >> 3, e = idx & 7;
        shw[e][k] = wg[idx];
    }
    __syncthreads();

    int warp = tid >> 5, lane = tid & 31;
    int s = blockIdx.x * 32 + warp;
    const float* xr = x + (size_t)s * MDIM;
    float* xo = g_xr + (size_t)s * MDIM;

    float acc[NEXP];
#pragma unroll
    for (int e = 0; e < NEXP; e++) acc[e] = 0.f;
#pragma unroll
    for (int i = 0; i < 8; i++) {
        float4 xv = *(const float4*)(xr + i * 128 + lane * 4);
#pragma unroll
        for (int e = 0; e < NEXP; e++) {
            float4 wv = *(const float4*)&shw[e][i * 128 + lane * 4];
            acc[e] += xv.x * wv.x + xv.y * wv.y + xv.z * wv.z + xv.w * wv.w;
        }
        float4 rv;
        rv.x = rna_tf32(xv.x); rv.y = rna_tf32(xv.y);
        rv.z = rna_tf32(xv.z); rv.w = rna_tf32(xv.w);
        *(float4*)(xo + i * 128 + lane * 4) = rv;
    }
#pragma unroll
    for (int e = 0; e < NEXP; e++) {
#pragma unroll
        for (int off = 16; off; off >>= 1)
            acc[e] += __shfl_xor_sync(0xffffffffu, acc[e], off);
    }
    if (lane == 0) {
        float best = acc[0]; int bi = 0;
#pragma unroll
        for (int e = 1; e < NEXP; e++)
            if (acc[e] > best) { best = acc[e]; bi = e; }
        float sum = 0.f;
#pragma unroll
        for (int e = 0; e < NEXP; e++) sum += __expf(acc[e] - best);
        g_expert_of_token[s] = bi;
        g_gate_of_token[s]   = 1.0f / sum;
    }
}

// ---------------- K2: per-expert rank scan + dropped-row zeroing ----------------
__global__ void scan_kernel(float* __restrict__ out) {
    int e = blockIdx.x;
    int t = threadIdx.x;             // 1024 threads
    int lane = t & 31, w = t >> 5;

    g_expert_tokens[e * CAP + t] = -1;
    g_gate_slot[e * CAP + t] = 0.f;

    int base = t * 8;
    int cnt = 0;
    int loc[8];
#pragma unroll
    for (int j = 0; j < 8; j++) {
        loc[j] = cnt;
        if (g_expert_of_token[base + j] == e) cnt++;
    }

    int incl = cnt;
#pragma unroll
    for (int off = 1; off < 32; off <<= 1) {
        int v = __shfl_up_sync(0xffffffffu, incl, off);
        if (lane >= off) incl += v;
    }
    __shared__ int wsum[32];
    __shared__ int ndrop;
    __shared__ int drop_list[S_TOK - CAP];
    if (t == 0) ndrop = 0;
    if (lane == 31) wsum[w] = incl;
    __syncthreads();
    if (w == 0) {
        int v2 = wsum[lane];
#pragma unroll
        for (int off = 1; off < 32; off <<= 1) {
            int u = __shfl_up_sync(0xffffffffu, v2, off);
            if (lane >= off) v2 += u;
        }
        wsum[lane] = v2;
    }
    __syncthreads();
    int excl = (w > 0 ? wsum[w - 1] : 0) + incl - cnt;

#pragma unroll
    for (int j = 0; j < 8; j++) {
        int s = base + j;
        if (g_expert_of_token[s] == e) {
            int c = excl + loc[j];
            if (c < CAP) {
                g_expert_tokens[e * CAP + c] = s;
                g_gate_slot[e * CAP + c]     = g_gate_of_token[s];
            } else {
                int d = atomicAdd(&ndrop, 1);
                drop_list[d] = s;
            }
        }
    }
    __syncthreads();

    int nd = ndrop;
    for (int d = 0; d < nd; d++) {
        int s = drop_list[d];
        out[(size_t)s * MDIM + t] = 0.f;
    }
}

// ---------------- K3: tf32 mma.sync GEMM — warp tile 128x32 (2M x 4N warps) ----------------
// C tile 256x128, BK=64, 8 warps, warp tile 128x32.
// A k-major in SMEM [256][68] (ldmatrix.x4, 8 frags/kk).
// B native row-major [64][136] (scalar LDS + cvt, 4 n-frags/kk).
#define BM 256
#define BN 128
#define BK 64
#define APAD 68
#define BPAD 136
#define A_FLOATS (BM * APAD)                          // 17408
#define B_FLOATS (BK * BPAD)                          // 8704
#define STAGE_B  ((A_FLOATS + B_FLOATS) * 4)          // 104448 bytes
#define TAB_OFF  (2 * STAGE_B)
#define GEMM_SMEM (2 * STAGE_B + BM * 8)              // +2KB ptr table

template<int K_TOTAL, int NDIM, bool IS_G2>
__global__ void __launch_bounds__(256, 1) mma_gemm(const float* __restrict__ W,
                                                   float* __restrict__ OUT) {
    constexpr int CITER = K_TOTAL / BK;
    extern __shared__ char smraw[];
    uint32_t sbase = smem_u32(smraw);
    const float** tab = (const float**)(smraw + TAB_OFF);

    int tid = threadIdx.x;
    int wid = tid >> 5, lane = tid & 31;
    int wm = wid & 1, wn = wid >> 1;     // 2 M-groups x 4 N-groups
    int g = lane >> 2, tg = lane & 3;

    int m0 = blockIdx.y * BM;
    int n0 = blockIdx.x * BN;
    int e  = m0 >> 10;

    const float* Wexp = W + (size_t)e * ((size_t)MDIM * FFN);

    // ---- G2: prefetch epilogue scatter metadata early (hide LDG latency) ----
    int ep_tokA[2], ep_tokB[2];
    float ep_gA[2], ep_gB[2];
    if (IS_G2) {
#pragma unroll
        for (int h = 0; h < 2; h++) {
            int r0 = m0 + wm * 128 + (h * 4) * 16 + g;   // rows for mi=0 and mi=4 groups
            (void)r0;
        }
        // prefetch the 16 per-warp scatter rows' metadata lazily per mi in epilogue;
        // prefetch the two base rows now to warm L2/L1
        int rbase = m0 + wm * 128 + g;
        ep_tokA[0] = g_expert_tokens[rbase];
        ep_gA[0]   = g_gate_slot[rbase];
        ep_tokB[0] = g_expert_tokens[rbase + 8];
        ep_gB[0]   = g_gate_slot[rbase + 8];
        ep_tokA[1] = ep_tokA[0]; ep_tokB[1] = ep_tokB[0];
        ep_gA[1] = ep_gA[0]; ep_gB[1] = ep_gB[0];
    }

    // ---- G1: gathered row-pointer table in SMEM ----
    if (!IS_G2) {
        int tok = g_expert_tokens[m0 + tid];
        tab[tid] = (tok >= 0) ? (g_xr + (size_t)tok * MDIM) : g_zero;
        __syncthreads();
    }

    // ---- affine cp.async addressing ----
    int arow = tid >> 4, ach = tid & 15;               // A: 16 rows/thread-group
    uint32_t daA = ((uint32_t)(arow * APAD + ach * 4)) * 4u;
    const float* Abase = IS_G2 ? (g_H + (size_t)(m0 + arow) * FFN + ach * 4) : nullptr;

    int brow = tid >> 5, bch = tid & 31;               // B: [64][128], 8 rows/thread-group
    uint32_t daB = ((uint32_t)(A_FLOATS + brow * BPAD + bch * 4)) * 4u;
    const float* Bbase = Wexp + (size_t)brow * NDIM + n0 + bch * 4;

    auto load_stage = [&](int s, int k0) {
        uint32_t sb = sbase + (uint32_t)s * STAGE_B;
#pragma unroll
        for (int i = 0; i < 16; i++) {
            uint32_t d = sb + daA + (uint32_t)i * (16 * APAD * 4);
            if (IS_G2) cp16(d, Abase + (size_t)i * (16 * FFN) + k0);
            else       cp16(d, tab[arow + 16 * i] + k0 + ach * 4);
        }
#pragma unroll
        for (int i = 0; i < 8; i++)
            cp16(sb + daB + (uint32_t)i * (8 * BPAD * 4),
                 Bbase + ((size_t)k0 + 8 * i) * NDIM);
        asm volatile("cp.async.commit_group;" ::: "memory");
    };

    load_stage(0, 0);

    // ---- ldmatrix per-lane A fragment addresses (8 M-tiles of 16 rows) ----
    uint32_t aoff[8];
    {
        uint32_t ar = (uint32_t)((lane & 7) + 8 * ((lane >> 3) & 1));
        uint32_t ac = (uint32_t)(((lane >> 4) & 1) * 4);
#pragma unroll
        for (int mi = 0; mi < 8; mi++)
            aoff[mi] = ((wm * 128 + mi * 16 + ar) * APAD + ac) * 4u;
    }

    float acc[8][4][4];
#pragma unroll
    for (int mi = 0; mi < 8; mi++)
#pragma unroll
        for (int ni = 0; ni < 4; ni++)
#pragma unroll
            for (int q = 0; q < 4; q++) acc[mi][ni][q] = 0.f;

    for (int c = 0; c < CITER; c++) {
        int s = c & 1;
        asm volatile("cp.async.wait_group 0;" ::: "memory");
        __syncthreads();
        if (c + 1 < CITER) load_stage(s ^ 1, (c + 1) * BK);

        uint32_t ab = sbase + (uint32_t)s * STAGE_B;
        const float* Bs = (const float*)(smraw + (size_t)s * STAGE_B) + A_FLOATS;

#pragma unroll
        for (int kk = 0; kk < 8; kk++) {
            int kb = kk * 8;
            // B fragments: 4 n-tiles (8 LDS + 8 CVT)
            uint32_t bf[4][2];
#pragma unroll
            for (int ni = 0; ni < 4; ni++) {
                int cc = wn * 32 + ni * 8 + g;
                bf[ni][0] = rna_tf32_u(Bs[(kb + tg) * BPAD + cc]);
                bf[ni][1] = rna_tf32_u(Bs[(kb + tg + 4) * BPAD + cc]);
            }
            // A fragments: 8 ldsm.x4
            uint32_t af[8][4];
#pragma unroll
            for (int mi = 0; mi < 8; mi++)
                ldsm4(af[mi], ab + aoff[mi] + (uint32_t)kk * 32);
#pragma unroll
            for (int mi = 0; mi < 8; mi++)
#pragma unroll
                for (int ni = 0; ni < 4; ni++)
                    mma_tf32(acc[mi][ni], af[mi], bf[ni]);
        }
    }

    // ---------------- epilogue ----------------
    if (!IS_G2) {
#pragma unroll
        for (int mi = 0; mi < 8; mi++) {
            int r0 = m0 + wm * 128 + mi * 16 + g;
#pragma unroll
            for (int ni = 0; ni < 4; ni++) {
                int cc = n0 + wn * 32 + ni * 8 + 2 * tg;
                float2 v0, v1;
                v0.x = rna_tf32(fmaxf(acc[mi][ni][0], 0.f));
                v0.y = rna_tf32(fmaxf(acc[mi][ni][1], 0.f));
                v1.x = rna_tf32(fmaxf(acc[mi][ni][2], 0.f));
                v1.y = rna_tf32(fmaxf(acc[mi][ni][3], 0.f));
                *(float2*)&g_H[(size_t)r0 * FFN + cc]       = v0;
                *(float2*)&g_H[(size_t)(r0 + 8) * FFN + cc] = v1;
            }
        }
    } else {
#pragma unroll
        for (int mi = 0; mi < 8; mi++) {
            int r0 = m0 + wm * 128 + mi * 16 + g;
            int tokA = (mi == 0) ? ep_tokA[0] : g_expert_tokens[r0];
            int tokB = (mi == 0) ? ep_tokB[0] : g_expert_tokens[r0 + 8];
            float gA = (mi == 0) ? ep_gA[0] : g_gate_slot[r0];
            float gB = (mi == 0) ? ep_gB[0] : g_gate_slot[r0 + 8];
#pragma unroll
            for (int ni = 0; ni < 4; ni++) {
                int cc = n0 + wn * 32 + ni * 8 + 2 * tg;
                if (tokA >= 0) {
                    float2 v; v.x = gA * acc[mi][ni][0]; v.y = gA * acc[mi][ni][1];
                    *(float2*)&OUT[(size_t)tokA * MDIM + cc] = v;
                }
                if (tokB >= 0) {
                    float2 v; v.x = gB * acc[mi][ni][2]; v.y = gB * acc[mi][ni][3];
                    *(float2*)&OUT[(size_t)tokB * MDIM + cc] = v;
                }
            }
        }
    }
}

// ---------------- launch ----------------
extern "C" void kernel_launch(void* const* d_in, const int* in_sizes, int n_in,
                              void* d_out, int out_size) {
    const float* x  = (const float*)d_in[0];
    const float* wg = (const float*)d_in[1];
    const float* w1 = (const float*)d_in[2];
    const float* w2 = (const float*)d_in[3];
    float* out = (float*)d_out;

    static bool attr_done = false;
    if (!attr_done) {
        cudaFuncSetAttribute(mma_gemm<MDIM, FFN,  false>,
                             cudaFuncAttributeMaxDynamicSharedMemorySize, GEMM_SMEM);
        cudaFuncSetAttribute(mma_gemm<FFN,  MDIM, true>,
                             cudaFuncAttributeMaxDynamicSharedMemorySize, GEMM_SMEM);
        attr_done = true;
    }

    gate_kernel<<<S_TOK / 32, 1024>>>(x, wg);
    scan_kernel<<<NEXP, 1024>>>(out);

    mma_gemm<MDIM, FFN,  false><<<dim3(FFN / BN,  (NEXP * CAP) / BM), 256, GEMM_SMEM>>>(w1, nullptr);
    mma_gemm<FFN,  MDIM, true ><<<dim3(MDIM / BN, (NEXP * CAP) / BM), 256, GEMM_SMEM>>>(w2, out);
}